// round 16
// baseline (speedup 1.0000x reference)
#include <cuda_runtime.h>
#include <cstdint>

// Problem constants
#define DN   16384
#define DD   128
#define DM1  64
#define DKK  8
#define NPC  8          // nodes per CTA
#define ROWTILE 256     // rows per CTA
#define THREADS 256     // 8 warps; warp = 32 rows x 64 cols; A in registers

// ---------------- device scratch (static, no allocs) ----------------
__device__ __align__(128) float g_Wc[DD * DM1 * DD];
__device__ __align__(128) float g_Xc[DN * DD];
__device__ float g_weffh[DD * DM1];   // 0.5 * weff
__device__ float g_beffh[DD * DM1];   // 0.5 * beff
__device__ float g_ceff2[DD];         // ceff + 0.5 * sum_m weff

// 16-col-group permutation: thread tg's frags for chunk pair (2c,2c+1) are
// the 16B at float offset 16c + 4*tg
__host__ __device__ __forceinline__ int perm16(int k) {
    return (k & ~15) | ((k & 3) << 2) | ((k >> 2) & 3);
}

__device__ __forceinline__ float to_tf32(float v) {
    uint32_t t;
    asm("cvt.rna.tf32.f32 %0, %1;" : "=r"(t) : "f"(v));
    return __uint_as_float(t);
}

__device__ __forceinline__ uint32_t smem_u32(const void* p) {
    uint32_t a;
    asm("{ .reg .u64 t; cvta.to.shared.u64 t, %1; cvt.u32.u64 %0, t; }" : "=r"(a) : "l"(p));
    return a;
}

__device__ __forceinline__ float tanha(float x) {
    float r;
    asm("tanh.approx.f32 %0, %1;" : "=f"(r) : "f"(x));
    return r;
}

__device__ __forceinline__ void mma_tf32(float* c, uint32_t a0, uint32_t a1, uint32_t a2,
                                         uint32_t a3, uint32_t b0, uint32_t b1) {
    asm volatile(
        "mma.sync.aligned.m16n8k8.row.col.f32.tf32.tf32.f32 "
        "{%0,%1,%2,%3}, {%4,%5,%6,%7}, {%8,%9}, {%0,%1,%2,%3};"
        : "+f"(c[0]), "+f"(c[1]), "+f"(c[2]), "+f"(c[3])
        : "r"(a0), "r"(a1), "r"(a2), "r"(a3), "r"(b0), "r"(b1));
}

__device__ __forceinline__ void cp16(uint32_t dst, const void* src) {
    asm volatile("cp.async.cg.shared.global [%0], [%1], 16;" :: "r"(dst), "l"(src) : "memory");
}
#define CP_COMMIT() asm volatile("cp.async.commit_group;" ::: "memory")
#define CP_WAIT0()  asm volatile("cp.async.wait_group 0;" ::: "memory")

// ---------------- precompute kernels ----------------
__global__ void prep_meta_kernel(const float* __restrict__ w2, const float* __restrict__ b2,
                                 const float* __restrict__ w3, const float* __restrict__ b1p,
                                 const float* __restrict__ b1n) {
    __shared__ float sw[DM1];
    int j = blockIdx.x;
    int m = threadIdx.x;
    float acc = 0.f;
#pragma unroll
    for (int k = 0; k < DKK; k++) acc += w3[j * DKK + k] * w2[k * DM1 + m];
    sw[m] = acc;
    g_weffh[j * DM1 + m] = 0.5f * acc;
    g_beffh[j * DM1 + m] = 0.5f * (b1p[j * DM1 + m] - b1n[j * DM1 + m]);
    __syncthreads();
    if (m == 0) {
        float c = 0.f;
#pragma unroll
        for (int k = 0; k < DKK; k++) c += w3[j * DKK + k] * b2[k];
        float s = 0.f;
#pragma unroll
        for (int t = 0; t < DM1; t++) s += sw[t];
        g_ceff2[j] = c + 0.5f * s;
    }
}

__global__ void prep_w_kernel(const float* __restrict__ w1p, const float* __restrict__ w1n) {
    int j = blockIdx.x;
    const float* p = w1p + (size_t)j * (DM1 * DD);
    const float* q = w1n + (size_t)j * (DM1 * DD);
    float* dst = g_Wc + (size_t)j * (DM1 * DD);
    for (int e = threadIdx.x; e < DM1 * DD; e += blockDim.x) {
        int m = e >> 7, k = e & 127;
        float v = p[e] - q[e];
        if (k == j) v = 0.f;
        dst[m * DD + perm16(k)] = to_tf32(v);
    }
}

__global__ void prep_x_kernel(const float* __restrict__ x) {
    size_t base = (size_t)blockIdx.x * (size_t)(128 * DD);
    const float* src = x + base;
    float* dst = g_Xc + base;
    for (int e = threadIdx.x; e < 128 * DD; e += blockDim.x) {
        int r = e >> 7, k = e & 127;
        dst[r * DD + perm16(k)] = to_tf32(src[e]);
    }
}

// ---------------- main fused kernel ----------------
// SMEM (floats), X row stride 144 (576B ≡ 64 mod 128 -> LDS.128 4-phase conflict-free)
// After A is copied to registers the X region [0, 36864) is DEAD and reused as
// a 2-slot acc staging area: slot s at float offset s*16384, value q (0..15) of
// thread tid at offset q*1024 + tid*4 (STS.128: consecutive lanes -> consecutive
// 16B -> conflict-free).
#define XSTR 144
#define WO   36864                      // W: 2 bufs x (64 x 144) = 18432
#define WBUF 9216
#define MBo  55296                      // 0.5*beff 8x64 = 512
#define MWo  55808                      // 0.5*weff 8x64 = 512
#define MCo  56320                      // ceff' 8
#define SMEM_FLOATS 56328
#define SMEM_BYTES  (SMEM_FLOATS * 4)   // 225312
#define SLOT_F 16384                    // floats per staging slot (64KB)

__device__ __forceinline__ void load_w_tile(uint32_t sb, int buf, int j, int tid) {
    const float4* src = (const float4*)(g_Wc + (size_t)j * (DM1 * DD));
#pragma unroll
    for (int e = tid; e < 2048; e += THREADS) {
        int m = e >> 5, c = e & 31;
        uint32_t dst = sb + (uint32_t)(WO * 4 + buf * (WBUF * 4) + m * (XSTR * 4) + c * 16);
        cp16(dst, src + e);
    }
}

// stage acc into slot (thread-private, conflict-free)
__device__ __forceinline__ void stage_acc(float* stgW, const float acc[2][8][4]) {
#pragma unroll
    for (int nt = 0; nt < 8; nt++)
#pragma unroll
        for (int mt = 0; mt < 2; mt++) {
            float4 v = make_float4(acc[mt][nt][0], acc[mt][nt][1],
                                   acc[mt][nt][2], acc[mt][nt][3]);
            *(float4*)(stgW + (nt * 2 + mt) * 1024) = v;
        }
}

// plain MMA (node with no staged predecessor); A fully in registers
__device__ __forceinline__ void mma_plain(const float* Wb, const float4 Ar[8][4],
                                          int g, int tg, float acc[2][8][4]) {
#pragma unroll
    for (int mt = 0; mt < 2; mt++)
#pragma unroll
        for (int nt = 0; nt < 8; nt++)
#pragma unroll
            for (int q = 0; q < 4; q++) acc[mt][nt][q] = 0.f;
#pragma unroll
    for (int c = 0; c < 8; c++) {
        const int off = c * 16 + 4 * tg;
        const float4 a00 = Ar[c][0], a01 = Ar[c][1], a10 = Ar[c][2], a11 = Ar[c][3];
#pragma unroll
        for (int nt = 0; nt < 8; nt++) {
            float4 b = *(const float4*)(Wb + (nt * 8 + g) * XSTR + off);
            uint32_t bx = __float_as_uint(b.x), by = __float_as_uint(b.y);
            uint32_t bz = __float_as_uint(b.z), bw = __float_as_uint(b.w);
            mma_tf32(acc[0][nt], __float_as_uint(a00.x), __float_as_uint(a01.x),
                     __float_as_uint(a00.y), __float_as_uint(a01.y), bx, by);
            mma_tf32(acc[1][nt], __float_as_uint(a10.x), __float_as_uint(a11.x),
                     __float_as_uint(a10.y), __float_as_uint(a11.y), bx, by);
            mma_tf32(acc[0][nt], __float_as_uint(a00.z), __float_as_uint(a01.z),
                     __float_as_uint(a00.w), __float_as_uint(a01.w), bz, bw);
            mma_tf32(acc[1][nt], __float_as_uint(a10.z), __float_as_uint(a11.z),
                     __float_as_uint(a10.w), __float_as_uint(a11.w), bz, bw);
        }
    }
}

// MMA for current node + interleaved staged epilogue of previous node.
// stgR: this thread's staging base in the slot holding prev node's acc.
// mwp/mbp: meta pointers for prev node. Produces p00..p11 partials.
__device__ __forceinline__ void mma_epi(const float* Wb, const float4 Ar[8][4],
                                        int g, int tg, float acc[2][8][4],
                                        const float* stgR,
                                        const float* mwp, const float* mbp,
                                        float& p00, float& p01, float& p10, float& p11) {
#pragma unroll
    for (int mt = 0; mt < 2; mt++)
#pragma unroll
        for (int nt = 0; nt < 8; nt++)
#pragma unroll
            for (int q = 0; q < 4; q++) acc[mt][nt][q] = 0.f;
    p00 = 0.f; p01 = 0.f; p10 = 0.f; p11 = 0.f;

#pragma unroll
    for (int c = 0; c < 8; c++) {
        const int off = c * 16 + 4 * tg;
        const float4 a00 = Ar[c][0], a01 = Ar[c][1], a10 = Ar[c][2], a11 = Ar[c][3];
#pragma unroll
        for (int nt = 0; nt < 8; nt++) {
            float4 b = *(const float4*)(Wb + (nt * 8 + g) * XSTR + off);
            uint32_t bx = __float_as_uint(b.x), by = __float_as_uint(b.y);
            uint32_t bz = __float_as_uint(b.z), bw = __float_as_uint(b.w);
            mma_tf32(acc[0][nt], __float_as_uint(a00.x), __float_as_uint(a01.x),
                     __float_as_uint(a00.y), __float_as_uint(a01.y), bx, by);
            mma_tf32(acc[1][nt], __float_as_uint(a10.x), __float_as_uint(a11.x),
                     __float_as_uint(a10.y), __float_as_uint(a11.y), bx, by);
            mma_tf32(acc[0][nt], __float_as_uint(a00.z), __float_as_uint(a01.z),
                     __float_as_uint(a00.w), __float_as_uint(a01.w), bz, bw);
            mma_tf32(acc[1][nt], __float_as_uint(a10.z), __float_as_uint(a11.z),
                     __float_as_uint(a10.w), __float_as_uint(a11.w), bz, bw);
        }
        // ---- epilogue slice nt=c for the PREVIOUS node (from smem staging) ----
        {
            const float4 s0 = *(const float4*)(stgR + (c * 2 + 0) * 1024);
            const float4 s1 = *(const float4*)(stgR + (c * 2 + 1) * 1024);
            const int c0 = c * 8 + 2 * tg;
            const float2 w2v = *(const float2*)(mwp + c0);
            const float2 b2v = *(const float2*)(mbp + c0);
            p00 += w2v.x * tanha(fmaf(s0.x, 0.5f, b2v.x))
                 + w2v.y * tanha(fmaf(s0.y, 0.5f, b2v.y));
            p01 += w2v.x * tanha(fmaf(s0.z, 0.5f, b2v.x))
                 + w2v.y * tanha(fmaf(s0.w, 0.5f, b2v.y));
            p10 += w2v.x * tanha(fmaf(s1.x, 0.5f, b2v.x))
                 + w2v.y * tanha(fmaf(s1.y, 0.5f, b2v.y));
            p11 += w2v.x * tanha(fmaf(s1.z, 0.5f, b2v.x))
                 + w2v.y * tanha(fmaf(s1.w, 0.5f, b2v.y));
        }
    }
}

// shuffle-reduce partials and store node jj's output column
__device__ __forceinline__ void finish_epi(const float* sm, float* __restrict__ out,
                                           int jj, int jbase, int rowg, int tg,
                                           float p00, float p01, float p10, float p11) {
    p00 += __shfl_xor_sync(0xFFFFFFFFu, p00, 1);
    p00 += __shfl_xor_sync(0xFFFFFFFFu, p00, 2);
    p01 += __shfl_xor_sync(0xFFFFFFFFu, p01, 1);
    p01 += __shfl_xor_sync(0xFFFFFFFFu, p01, 2);
    p10 += __shfl_xor_sync(0xFFFFFFFFu, p10, 1);
    p10 += __shfl_xor_sync(0xFFFFFFFFu, p10, 2);
    p11 += __shfl_xor_sync(0xFFFFFFFFu, p11, 1);
    p11 += __shfl_xor_sync(0xFFFFFFFFu, p11, 2);
    if (tg == 0) {
        float ce = sm[MCo + jj];
        float* o = out + (size_t)rowg * DD + jbase + jj;
        o[0 * DD]  = p00 + ce;
        o[8 * DD]  = p01 + ce;
        o[16 * DD] = p10 + ce;
        o[24 * DD] = p11 + ce;
    }
}

// direct epilogue from registers (last node only)
__device__ __forceinline__ void epi_direct(const float* sm, float* __restrict__ out,
                                           const float acc[2][8][4],
                                           int jj, int jbase, int rowg, int tg) {
    const float* mb = sm + MBo + jj * DM1;
    const float* mw = sm + MWo + jj * DM1;
    float p00 = 0.f, p01 = 0.f, p10 = 0.f, p11 = 0.f;
#pragma unroll
    for (int nt = 0; nt < 8; nt++) {
        int c0 = nt * 8 + 2 * tg;
        float2 w2v = *(const float2*)(mw + c0);
        float2 b2v = *(const float2*)(mb + c0);
        p00 += w2v.x * tanha(fmaf(acc[0][nt][0], 0.5f, b2v.x))
             + w2v.y * tanha(fmaf(acc[0][nt][1], 0.5f, b2v.y));
        p01 += w2v.x * tanha(fmaf(acc[0][nt][2], 0.5f, b2v.x))
             + w2v.y * tanha(fmaf(acc[0][nt][3], 0.5f, b2v.y));
        p10 += w2v.x * tanha(fmaf(acc[1][nt][0], 0.5f, b2v.x))
             + w2v.y * tanha(fmaf(acc[1][nt][1], 0.5f, b2v.y));
        p11 += w2v.x * tanha(fmaf(acc[1][nt][2], 0.5f, b2v.x))
             + w2v.y * tanha(fmaf(acc[1][nt][3], 0.5f, b2v.y));
    }
    finish_epi(sm, out, jj, jbase, rowg, tg, p00, p01, p10, p11);
}

__global__ void __launch_bounds__(THREADS, 1)
fused_dag_kernel(float* __restrict__ out) {
    extern __shared__ float sm[];
    const uint32_t sb = smem_u32(sm);
    const int tid = threadIdx.x;
    const int w = tid >> 5;                // 0..7 : rows w*32..w*32+31
    const int lane = tid & 31;
    const int g = lane >> 2;
    const int tg = lane & 3;
    const int tileR = blockIdx.x;          // 0..63
    const int jbase = blockIdx.y * NPC;

    // ---- async loads: X tile + W buf0 ----
    {
        const float4* src = (const float4*)(g_Xc + (size_t)tileR * (ROWTILE * DD));
#pragma unroll
        for (int e = tid; e < 8192; e += THREADS) {
            int r = e >> 5, c = e & 31;
            uint32_t dst = sb + (uint32_t)(r * (XSTR * 4) + c * 16);
            cp16(dst, src + e);
        }
    }
    load_w_tile(sb, 0, jbase, tid);
    CP_COMMIT();

    // ---- meta into smem ----
#pragma unroll
    for (int e = tid; e < NPC * DM1; e += THREADS) {
        int jj = e >> 6, m = e & 63;
        int j = jbase + jj;
        sm[MBo + e] = g_beffh[j * DM1 + m];
        sm[MWo + e] = g_weffh[j * DM1 + m];
    }
    if (tid < NPC) sm[MCo + tid] = g_ceff2[jbase + tid];

    const int rbase = w * 32;
    const float* Xm0r0 = sm + (rbase + g) * XSTR;
    const float* Xm0r1 = Xm0r0 + 8 * XSTR;
    const float* Xm1r0 = Xm0r0 + 16 * XSTR;
    const float* Xm1r1 = Xm0r0 + 24 * XSTR;
    const int rowg = tileR * ROWTILE + rbase + g;

    CP_WAIT0();
    __syncthreads();

    // ---- ALL A fragments into registers ONCE; X smem is DEAD after this ----
    float4 Ar[8][4];
#pragma unroll
    for (int c = 0; c < 8; c++) {
        const int off = c * 16 + 4 * tg;
        Ar[c][0] = *(const float4*)(Xm0r0 + off);
        Ar[c][1] = *(const float4*)(Xm0r1 + off);
        Ar[c][2] = *(const float4*)(Xm1r0 + off);
        Ar[c][3] = *(const float4*)(Xm1r1 + off);
    }
    __syncthreads();   // all A reads done before any staging overwrites X region

    float acc[2][8][4];   // single static accumulator set

    // ---- node 0: plain MMA, stage acc into slot 0 ----
    load_w_tile(sb, 1, jbase + 1, tid);
    CP_COMMIT();
    mma_plain(sm + WO, Ar, g, tg, acc);
    stage_acc(sm + 0 * SLOT_F + tid * 4, acc);

    // ---- nodes 1..7: MMA(i) with interleaved staged epilogue(i-1) ----
#pragma unroll 1
    for (int i = 1; i < NPC; i++) {
        CP_WAIT0();
        __syncthreads();
        if (i + 1 < NPC) { load_w_tile(sb, (i + 1) & 1, jbase + i + 1, tid); CP_COMMIT(); }
        const float* Wb  = sm + WO + (i & 1) * WBUF;
        const float* stgR = sm + ((i - 1) & 1) * SLOT_F + tid * 4;
        const float* mwp = sm + MWo + (i - 1) * DM1;
        const float* mbp = sm + MBo + (i - 1) * DM1;
        float p00, p01, p10, p11;
        mma_epi(Wb, Ar, g, tg, acc, stgR, mwp, mbp, p00, p01, p10, p11);
        finish_epi(sm, out, i - 1, jbase, rowg, tg, p00, p01, p10, p11);
        if (i < NPC - 1) stage_acc(sm + (i & 1) * SLOT_F + tid * 4, acc);
    }
    // ---- tail: node 7 epilogue directly from registers ----
    epi_direct(sm, out, acc, NPC - 1, jbase, rowg, tg);
}

// ---------------- launch ----------------
extern "C" void kernel_launch(void* const* d_in, const int* in_sizes, int n_in,
                              void* d_out, int out_size) {
    const float* x   = (const float*)d_in[0];
    const float* w1p = (const float*)d_in[1];
    const float* b1p = (const float*)d_in[2];
    const float* w1n = (const float*)d_in[3];
    const float* b1n = (const float*)d_in[4];
    const float* w2  = (const float*)d_in[5];
    const float* b2  = (const float*)d_in[6];
    const float* w3  = (const float*)d_in[7];
    float* out = (float*)d_out;

    prep_meta_kernel<<<DD, DM1>>>(w2, b2, w3, b1p, b1n);
    prep_w_kernel<<<DD, 256>>>(w1p, w1n);
    prep_x_kernel<<<DN / 128, 256>>>(x);

    cudaFuncSetAttribute(fused_dag_kernel, cudaFuncAttributeMaxDynamicSharedMemorySize,
                         SMEM_BYTES);
    dim3 grid(DN / ROWTILE, DD / NPC);
    fused_dag_kernel<<<grid, THREADS, SMEM_BYTES>>>(out);
}

// round 17
// speedup vs baseline: 1.5511x; 1.5511x over previous
#include <cuda_runtime.h>
#include <cstdint>

// Problem constants
#define DN   16384
#define DD   128
#define DM1  64
#define DKK  8
#define NPC  8          // nodes per CTA
#define ROWTILE 256     // rows per CTA
#define THREADS 512     // 16 warps; warp = 16 rows x 64 cols; A in registers

// ---------------- device scratch (static, no allocs) ----------------
__device__ __align__(128) float g_Wc[DD * DM1 * DD];
__device__ __align__(128) float g_Xc[DN * DD];
__device__ float g_weffh[DD * DM1];   // 0.5 * weff
__device__ float g_beffh[DD * DM1];   // 0.5 * beff
__device__ float g_ceff2[DD];         // ceff + 0.5 * sum_m weff

// 16-col-group permutation: thread tg's frags for chunk pair (2c,2c+1) are
// the 16B at float offset 16c + 4*tg
__host__ __device__ __forceinline__ int perm16(int k) {
    return (k & ~15) | ((k & 3) << 2) | ((k >> 2) & 3);
}

__device__ __forceinline__ float to_tf32(float v) {
    uint32_t t;
    asm("cvt.rna.tf32.f32 %0, %1;" : "=r"(t) : "f"(v));
    return __uint_as_float(t);
}

__device__ __forceinline__ uint32_t smem_u32(const void* p) {
    uint32_t a;
    asm("{ .reg .u64 t; cvta.to.shared.u64 t, %1; cvt.u32.u64 %0, t; }" : "=r"(a) : "l"(p));
    return a;
}

__device__ __forceinline__ float tanha(float x) {
    float r;
    asm("tanh.approx.f32 %0, %1;" : "=f"(r) : "f"(x));
    return r;
}

__device__ __forceinline__ void mma_tf32(float* c, uint32_t a0, uint32_t a1, uint32_t a2,
                                         uint32_t a3, uint32_t b0, uint32_t b1) {
    asm volatile(
        "mma.sync.aligned.m16n8k8.row.col.f32.tf32.tf32.f32 "
        "{%0,%1,%2,%3}, {%4,%5,%6,%7}, {%8,%9}, {%0,%1,%2,%3};"
        : "+f"(c[0]), "+f"(c[1]), "+f"(c[2]), "+f"(c[3])
        : "r"(a0), "r"(a1), "r"(a2), "r"(a3), "r"(b0), "r"(b1));
}

__device__ __forceinline__ void cp16(uint32_t dst, const void* src) {
    asm volatile("cp.async.cg.shared.global [%0], [%1], 16;" :: "r"(dst), "l"(src) : "memory");
}
#define CP_COMMIT() asm volatile("cp.async.commit_group;" ::: "memory")
#define CP_WAIT0()  asm volatile("cp.async.wait_group 0;" ::: "memory")

// ---------------- precompute kernels ----------------
__global__ void prep_meta_kernel(const float* __restrict__ w2, const float* __restrict__ b2,
                                 const float* __restrict__ w3, const float* __restrict__ b1p,
                                 const float* __restrict__ b1n) {
    __shared__ float sw[DM1];
    int j = blockIdx.x;
    int m = threadIdx.x;
    float acc = 0.f;
#pragma unroll
    for (int k = 0; k < DKK; k++) acc += w3[j * DKK + k] * w2[k * DM1 + m];
    sw[m] = acc;
    g_weffh[j * DM1 + m] = 0.5f * acc;
    g_beffh[j * DM1 + m] = 0.5f * (b1p[j * DM1 + m] - b1n[j * DM1 + m]);
    __syncthreads();
    if (m == 0) {
        float c = 0.f;
#pragma unroll
        for (int k = 0; k < DKK; k++) c += w3[j * DKK + k] * b2[k];
        float s = 0.f;
#pragma unroll
        for (int t = 0; t < DM1; t++) s += sw[t];
        g_ceff2[j] = c + 0.5f * s;
    }
}

__global__ void prep_w_kernel(const float* __restrict__ w1p, const float* __restrict__ w1n) {
    int j = blockIdx.x;
    const float* p = w1p + (size_t)j * (DM1 * DD);
    const float* q = w1n + (size_t)j * (DM1 * DD);
    float* dst = g_Wc + (size_t)j * (DM1 * DD);
    for (int e = threadIdx.x; e < DM1 * DD; e += blockDim.x) {
        int m = e >> 7, k = e & 127;
        float v = p[e] - q[e];
        if (k == j) v = 0.f;
        dst[m * DD + perm16(k)] = to_tf32(v);
    }
}

__global__ void prep_x_kernel(const float* __restrict__ x) {
    size_t base = (size_t)blockIdx.x * (size_t)(128 * DD);
    const float* src = x + base;
    float* dst = g_Xc + base;
    for (int e = threadIdx.x; e < 128 * DD; e += blockDim.x) {
        int r = e >> 7, k = e & 127;
        dst[r * DD + perm16(k)] = to_tf32(src[e]);
    }
}

// ---------------- main fused kernel ----------------
// SMEM (floats), X row stride 144 (576B ≡ 64 mod 128 -> LDS.128 4-phase conflict-free)
#define XSTR 144
#define WO   36864                      // W: 2 bufs x (64 x 144) = 18432
#define WBUF 9216
#define MBo  55296                      // 0.5*beff 8x64 = 512
#define MWo  55808                      // 0.5*weff 8x64 = 512
#define MCo  56320                      // ceff' 8
#define SMEM_FLOATS 56328
#define SMEM_BYTES  (SMEM_FLOATS * 4)   // 225312

__device__ __forceinline__ void load_w_tile(uint32_t sb, int buf, int j, int tid) {
    const float4* src = (const float4*)(g_Wc + (size_t)j * (DM1 * DD));
#pragma unroll
    for (int e = tid; e < 2048; e += THREADS) {
        int m = e >> 5, c = e & 31;
        uint32_t dst = sb + (uint32_t)(WO * 4 + buf * (WBUF * 4) + m * (XSTR * 4) + c * 16);
        cp16(dst, src + e);
    }
}

__global__ void __launch_bounds__(THREADS, 1)
fused_dag_kernel(float* __restrict__ out) {
    extern __shared__ float sm[];
    const uint32_t sb = smem_u32(sm);
    const int tid = threadIdx.x;
    const int w = tid >> 5;                // 0..15 : rows w*16..w*16+15
    const int lane = tid & 31;
    const int g = lane >> 2;
    const int tg = lane & 3;
    const int tileR = blockIdx.x;          // 0..63
    const int jbase = blockIdx.y * NPC;

    // ---- async loads: X tile + W buf0 ----
    {
        const float4* src = (const float4*)(g_Xc + (size_t)tileR * (ROWTILE * DD));
#pragma unroll
        for (int e = tid; e < 8192; e += THREADS) {
            int r = e >> 5, c = e & 31;
            uint32_t dst = sb + (uint32_t)(r * (XSTR * 4) + c * 16);
            cp16(dst, src + e);
        }
    }
    load_w_tile(sb, 0, jbase, tid);
    CP_COMMIT();

    // ---- meta into smem ----
    if (tid < NPC * DM1) {
        int jj = tid >> 6, m = tid & 63;
        int j = jbase + jj;
        sm[MBo + tid] = g_beffh[j * DM1 + m];
        sm[MWo + tid] = g_weffh[j * DM1 + m];
    }
    if (tid < NPC) sm[MCo + tid] = g_ceff2[jbase + tid];

    const int rbase = w * 16;
    const float* Xr0 = sm + (rbase + g) * XSTR;       // row rbase+g
    const float* Xr1 = Xr0 + 8 * XSTR;                // row rbase+g+8
    const int rowg = tileR * ROWTILE + rbase + g;

    CP_WAIT0();
    __syncthreads();

    // ---- A fragments (16 rows) into registers ONCE: 16 x float4 = 64 regs ----
    float4 Ar0[8], Ar1[8];
#pragma unroll
    for (int c = 0; c < 8; c++) {
        const int off = c * 16 + 4 * tg;
        Ar0[c] = *(const float4*)(Xr0 + off);
        Ar1[c] = *(const float4*)(Xr1 + off);
    }

#pragma unroll 1
    for (int i = 0; i < NPC; i++) {
        if (i > 0) CP_WAIT0();
        __syncthreads();
        if (i + 1 < NPC) { load_w_tile(sb, (i + 1) & 1, jbase + i + 1, tid); CP_COMMIT(); }

        const float* Wb = sm + WO + (i & 1) * WBUF;

        float acc[8][4];
#pragma unroll
        for (int nt = 0; nt < 8; nt++)
#pragma unroll
            for (int q = 0; q < 4; q++) acc[nt][q] = 0.f;

#pragma unroll
        for (int c = 0; c < 8; c++) {           // chunk pair 2c, 2c+1
            const int off = c * 16 + 4 * tg;
            const float4 a0 = Ar0[c];
            const float4 a1 = Ar1[c];
#pragma unroll
            for (int nt = 0; nt < 8; nt++) {
                float4 b = *(const float4*)(Wb + (nt * 8 + g) * XSTR + off);
                mma_tf32(acc[nt], __float_as_uint(a0.x), __float_as_uint(a1.x),
                         __float_as_uint(a0.y), __float_as_uint(a1.y),
                         __float_as_uint(b.x), __float_as_uint(b.y));
                mma_tf32(acc[nt], __float_as_uint(a0.z), __float_as_uint(a1.z),
                         __float_as_uint(a0.w), __float_as_uint(a1.w),
                         __float_as_uint(b.z), __float_as_uint(b.w));
            }
        }

        // ---- epilogue: w*sig(h) = wh + wh*tanh(0.5h'); wh-sum folded into ceff' ----
        {
            const float* mb = sm + MBo + i * DM1;
            const float* mw = sm + MWo + i * DM1;
            float p0 = 0.f, p1 = 0.f;
#pragma unroll
            for (int nt = 0; nt < 8; nt++) {
                int c0 = nt * 8 + 2 * tg;
                float2 w2v = *(const float2*)(mw + c0);
                float2 b2v = *(const float2*)(mb + c0);
                p0 += w2v.x * tanha(fmaf(acc[nt][0], 0.5f, b2v.x))
                    + w2v.y * tanha(fmaf(acc[nt][1], 0.5f, b2v.y));
                p1 += w2v.x * tanha(fmaf(acc[nt][2], 0.5f, b2v.x))
                    + w2v.y * tanha(fmaf(acc[nt][3], 0.5f, b2v.y));
            }
            p0 += __shfl_xor_sync(0xFFFFFFFFu, p0, 1);
            p0 += __shfl_xor_sync(0xFFFFFFFFu, p0, 2);
            p1 += __shfl_xor_sync(0xFFFFFFFFu, p1, 1);
            p1 += __shfl_xor_sync(0xFFFFFFFFu, p1, 2);
            if (tg == 0) {
                float ce = sm[MCo + i];
                float* o = out + (size_t)rowg * DD + jbase + i;
                o[0 * DD] = p0 + ce;
                o[8 * DD] = p1 + ce;
            }
        }
    }
}

// ---------------- launch ----------------
extern "C" void kernel_launch(void* const* d_in, const int* in_sizes, int n_in,
                              void* d_out, int out_size) {
    const float* x   = (const float*)d_in[0];
    const float* w1p = (const float*)d_in[1];
    const float* b1p = (const float*)d_in[2];
    const float* w1n = (const float*)d_in[3];
    const float* b1n = (const float*)d_in[4];
    const float* w2  = (const float*)d_in[5];
    const float* b2  = (const float*)d_in[6];
    const float* w3  = (const float*)d_in[7];
    float* out = (float*)d_out;

    prep_meta_kernel<<<DD, DM1>>>(w2, b2, w3, b1p, b1n);
    prep_w_kernel<<<DD, 256>>>(w1p, w1n);
    prep_x_kernel<<<DN / 128, 256>>>(x);

    cudaFuncSetAttribute(fused_dag_kernel, cudaFuncAttributeMaxDynamicSharedMemorySize,
                         SMEM_BYTES);
    dim3 grid(DN / ROWTILE, DD / NPC);
    fused_dag_kernel<<<grid, THREADS, SMEM_BYTES>>>(out);
}